// round 9
// baseline (speedup 1.0000x reference)
#include <cuda_runtime.h>
#include <math.h>

#define LSEQ   8192
#define NBATCH 1024
#define NT     512
#define NSTATE 64
#define PI_F 3.14159265358979323846f

// Skewed smem layout: +1 float2 per 8 -> removes stage-0 (8-way) and
// stage-1 (2-way) store bank conflicts of the Stockham scatter.
#define PD(i) ((i) + ((i) >> 3))
#define PDSZ 9216          // PD(8191)=9214 < 9216

__device__ float2 g_wm[16384];   // WM[k] = exp(-2*pi*i*k/16384)
__device__ float2 g_kh[4100];    // K_hat spectrum bins 0..4096
__device__ float2 g_kf[8200];    // rfft_16384 of padded K, bins 0..8192

// ---------------- complex helpers ----------------
static __device__ __forceinline__ float2 cmul(float2 a, float2 b) {
    return make_float2(a.x*b.x - a.y*b.y, a.x*b.y + a.y*b.x);
}
static __device__ __forceinline__ float2 cadd(float2 a, float2 b){ return make_float2(a.x+b.x, a.y+b.y); }
static __device__ __forceinline__ float2 csub(float2 a, float2 b){ return make_float2(a.x-b.x, a.y-b.y); }
static __device__ __forceinline__ float2 cconj(float2 a){ return make_float2(a.x, -a.y); }
static __device__ __forceinline__ float2 cscale(float2 a, float s){ return make_float2(a.x*s, a.y*s); }

// ---------------- merged setup (ALL fp32 — fp64 pipe on B300 is poison) ----------------
__global__ void setup_kernel(const float* __restrict__ Bv, const float* __restrict__ Cv) {
    if (blockIdx.x > 4096) {
        int k = (blockIdx.x - 4097) * 64 + threadIdx.x;   // 0..16383
        float s, c;
        sincospif((float)k / 8192.0f, &s, &c);            // angle = 2*pi*k/16384
        g_wm[k] = make_float2(c, -s);
        return;
    }
    __shared__ float shg[5];
    __shared__ float wsum[2][8];
    int f = blockIdx.x;              // 0..4096
    int n = threadIdx.x;             // 0..63
    if (n == 0) {
        // sincosf (fp32): at f=4096 sin(float(pi)) ~ -8.74e-8 != 0 -> no NaN.
        float th = (2.0f * PI_F / 8192.0f) * (float)f;
        float s, c;
        sincosf(th, &s, &c);                              // omega = c + i s
        float nr = 1.0f - c, ni = -s;
        float dr = 1.0f + c, di = s;
        float dd = dr*dr + di*di;
        shg[0] = 20.0f * (nr*dr + ni*di) / dd;
        shg[1] = 20.0f * (ni*dr - nr*di) / dd;
        shg[2] = dr; shg[3] = di; shg[4] = dd;
    }
    __syncthreads();
    float gr = shg[0], gi = shg[1];
    float er = gr + 0.5f;
    float ei = gi - PI_F * (float)n;
    float inv = 1.0f / (er*er + ei*ei);
    float ir =  er * inv, ii = -ei * inv;
    float b0 = Bv[n];
    float a0 = Cv[n];
    float p2 = (float)n + 0.5f;
    float p  = sqrtf(p2);
    float v00 = a0*b0, v01 = a0*p, v10 = p*b0, v11 = p2;
    float acc[8] = { v00*ir, v00*ii, v01*ir, v01*ii,
                     v10*ir, v10*ii, v11*ir, v11*ii };
    #pragma unroll
    for (int off = 16; off; off >>= 1) {
        #pragma unroll
        for (int t = 0; t < 8; t++)
            acc[t] += __shfl_down_sync(0xffffffffu, acc[t], off);
    }
    if ((n & 31) == 0) {
        #pragma unroll
        for (int t = 0; t < 8; t++) wsum[n >> 5][t] = acc[t];
    }
    __syncthreads();
    if (n == 0) {
        float k00r = wsum[0][0]+wsum[1][0], k00i = wsum[0][1]+wsum[1][1];
        float k01r = wsum[0][2]+wsum[1][2], k01i = wsum[0][3]+wsum[1][3];
        float k10r = wsum[0][4]+wsum[1][4], k10i = wsum[0][5]+wsum[1][5];
        float k11r = wsum[0][6]+wsum[1][6], k11i = wsum[0][7]+wsum[1][7];
        float ur = 1.0f + k11r, ui = k11i;
        float t1r = k01r*ur - k01i*ui, t1i = k01r*ui + k01i*ur;
        float t2r = t1r*k10r - t1i*k10i, t2i = t1r*k10i + t1i*k10r;
        float hr = k00r - t2r, hi = k00i - t2i;
        float dr = shg[2], di = shg[3], dd = shg[4];
        float c2r = 2.0f*dr/dd, c2i = -2.0f*di/dd;
        g_kh[f] = make_float2(c2r*hr - c2i*hi, c2r*hi + c2i*hr);
    }
}

// ---------------- radix-8 Stockham FFT, N=8192, forward, PD-skewed smem ----------------
// 4 radix-8 stages + final radix-2. Reads A (PD layout), result in B (PD layout).
template<int NTH, bool ZHI, bool SKIPHI>
static __device__ __forceinline__ void fft8192_r8(float2* A, float2* B, int tid) {
    float2* src = A;
    float2* dst = B;
    #pragma unroll
    for (int st = 0; st < 4; st++) {
        const int ls = 3 * st;            // log2(s): 0,3,6,9
        const int s  = 1 << ls;           // 1,8,64,512
        #pragma unroll
        for (int it = 0; it < 1024 / NTH; it++) {
            int idx = tid + it * NTH;     // < 1024
            int p = idx >> ls;
            int q = idx & (s - 1);
            float2 x0 = src[PD(idx)];
            float2 x1 = src[PD(idx + 1024)];
            float2 x2 = src[PD(idx + 2048)];
            float2 x3 = src[PD(idx + 3072)];
            float2 x4, x5, x6, x7;
            if (ZHI && st == 0) {
                x4 = x5 = x6 = x7 = make_float2(0.f, 0.f);
            } else {
                x4 = src[PD(idx + 4096)];
                x5 = src[PD(idx + 5120)];
                x6 = src[PD(idx + 6144)];
                x7 = src[PD(idx + 7168)];
            }
            // DFT8
            float2 ea = cadd(x0, x4), em = csub(x0, x4);
            float2 eb = cadd(x2, x6), en = csub(x2, x6);
            float2 ej = make_float2(-en.y, en.x);
            float2 E0 = cadd(ea, eb), E1 = csub(em, ej);
            float2 E2 = csub(ea, eb), E3 = cadd(em, ej);
            float2 oa = cadd(x1, x5), om = csub(x1, x5);
            float2 ob = cadd(x3, x7), on = csub(x3, x7);
            float2 oj = make_float2(-on.y, on.x);
            float2 O0 = cadd(oa, ob), O1 = csub(om, oj);
            float2 O2 = csub(oa, ob), O3 = cadd(om, oj);
            const float C = 0.70710678118654752440f;
            float2 t0 = O0;
            float2 t1 = make_float2(C*(O1.x + O1.y), C*(O1.y - O1.x));
            float2 t2 = make_float2(O2.y, -O2.x);
            float2 t3 = make_float2(C*(O3.y - O3.x), -C*(O3.x + O3.y));
            float2 X0 = cadd(E0, t0), X4 = csub(E0, t0);
            float2 X1 = cadd(E1, t1), X5 = csub(E1, t1);
            float2 X2 = cadd(E2, t2), X6 = csub(E2, t2);
            float2 X3 = cadd(E3, t3), X7 = csub(E3, t3);
            // twiddles: w_j = exp(-2*pi*i*p*s*j/8192) = g_wm[2*p*s*j]
            int tw = (p << (ls + 1));
            float2 w1 = g_wm[tw];
            float2 w2 = cmul(w1, w1);
            float2 w3 = cmul(w2, w1);
            float2 w4 = cmul(w2, w2);
            float2 w5 = cmul(w3, w2);
            float2 w6 = cmul(w3, w3);
            float2 w7 = cmul(w4, w3);
            int o = q + (p << (ls + 3));
            dst[PD(o)]       = X0;
            dst[PD(o + s)]   = cmul(w1, X1);
            dst[PD(o + 2*s)] = cmul(w2, X2);
            dst[PD(o + 3*s)] = cmul(w3, X3);
            dst[PD(o + 4*s)] = cmul(w4, X4);
            dst[PD(o + 5*s)] = cmul(w5, X5);
            dst[PD(o + 6*s)] = cmul(w6, X6);
            dst[PD(o + 7*s)] = cmul(w7, X7);
        }
        __syncthreads();
        float2* t = src; src = dst; dst = t;
    }
    // After 4 swaps: src == A, dst == B. Final radix-2 (p=0, twiddle-free).
    #pragma unroll
    for (int it = 0; it < 4096 / NTH; it++) {
        int q = tid + it * NTH;
        float2 a = src[PD(q)], b = src[PD(q + 4096)];
        dst[PD(q)] = cadd(a, b);
        if (!SKIPHI) dst[PD(q + 4096)] = csub(a, b);
    }
    __syncthreads();
}

// ---------------- K preparation ----------------
__global__ void kprep_kernel() {
    extern __shared__ float2 sm[];
    float2* A = sm;
    float2* B = sm + PDSZ;
    int tid = threadIdx.x;

    #pragma unroll
    for (int it = 0; it < 16; it++) {
        int f = tid + it * NT;
        float2 kh = (f <= 4096) ? g_kh[f] : g_kh[8192 - f];
        A[PD(f)] = (f <= 4096) ? cconj(kh) : kh;
    }
    __syncthreads();
    fft8192_r8<NT, false, false>(A, B, tid);
    const float sc = 1.0f / 8192.0f;
    #pragma unroll
    for (int it = 0; it < 8; it++) {
        int j = tid + it * NT;   // j < 4096
        A[PD(j)] = make_float2(B[PD(2*j)].x * sc, B[PD(2*j + 1)].x * sc);
    }
    __syncthreads();
    fft8192_r8<NT, true, false>(A, B, tid);
    for (int k = tid; k <= 4096; k += NT) {
        if (k == 0) {
            float2 Z0 = B[PD(0)];
            g_kf[0]    = make_float2(Z0.x + Z0.y, 0.f);
            g_kf[8192] = make_float2(Z0.x - Z0.y, 0.f);
        } else {
            int hk = 8192 - k;
            float2 Zk  = B[PD(k)];
            float2 Zhc = cconj(B[PD(hk)]);
            float2 E  = cscale(cadd(Zk, Zhc), 0.5f);
            float2 Om = csub(Zk, Zhc);
            float2 O  = make_float2(0.5f * Om.y, -0.5f * Om.x);
            float2 w  = g_wm[k];
            g_kf[k] = cadd(E, cmul(w, O));
            if (k != 4096) {
                float2 wh = make_float2(-w.x, w.y);
                g_kf[hk] = cadd(cconj(E), cmul(wh, cconj(O)));
            }
        }
    }
}

// ---------------- main batched FFT convolution ----------------
__global__ void __launch_bounds__(NT, 1) conv_kernel(const float* __restrict__ x,
                                                     float* __restrict__ y) {
    extern __shared__ float2 sm[];
    float2* A = sm;
    float2* B = sm + PDSZ;
    int b = blockIdx.x;
    int tid = threadIdx.x;

    const float2* xr = (const float2*)(x + (size_t)b * LSEQ);
    #pragma unroll
    for (int it = 0; it < 8; it++) {
        int j = tid + it * NT;   // j < 4096
        A[PD(j)] = xr[j];
    }
    __syncthreads();

    fft8192_r8<NT, true, false>(A, B, tid);   // Z in B

    for (int k = tid; k <= 4096; k += NT) {
        if (k == 0) {
            float2 Z0 = B[PD(0)];
            float X0 = Z0.x + Z0.y;
            float XH = Z0.x - Z0.y;
            float2 Y0 = cscale(g_kf[0], X0);
            float2 YH = cscale(g_kf[8192], XH);
            float2 Yhc = cconj(YH);
            float2 S = cscale(cadd(Y0, Yhc), 0.5f);
            float2 D = cscale(csub(Y0, Yhc), 0.5f);
            float2 Zy0 = make_float2(S.x - D.y, S.y + D.x);
            A[PD(0)] = cconj(Zy0);
        } else {
            int hk = 8192 - k;
            float2 Zk  = B[PD(k)];
            float2 Zhc = cconj(B[PD(hk)]);
            float2 E  = cscale(cadd(Zk, Zhc), 0.5f);
            float2 Om = csub(Zk, Zhc);
            float2 O  = make_float2(0.5f * Om.y, -0.5f * Om.x);
            float2 w  = g_wm[k];
            float2 Xk = cadd(E, cmul(w, O));
            float2 wh = make_float2(-w.x, w.y);
            float2 Xh = cadd(cconj(E), cmul(wh, cconj(O)));
            float2 Yk = cmul(Xk, g_kf[k]);
            float2 Yh = cmul(Xh, g_kf[hk]);
            float2 Yhc = cconj(Yh);
            float2 S = cscale(cadd(Yk, Yhc), 0.5f);
            float2 D = cscale(csub(Yk, Yhc), 0.5f);
            float2 u = cmul(cconj(w), D);
            float2 Zyk = make_float2(S.x - u.y, S.y + u.x);
            A[PD(k)] = cconj(Zyk);
            if (k != 4096) {
                float2 Ykc = cconj(Yk);
                float2 S2 = cscale(cadd(Yh, Ykc), 0.5f);
                float2 D2 = cscale(csub(Yh, Ykc), 0.5f);
                float2 v = cmul(w, D2);
                float2 Zyh = make_float2(S2.x + v.y, S2.y - v.x);
                A[PD(hk)] = cconj(Zyh);
            }
        }
    }
    __syncthreads();

    fft8192_r8<NT, false, true>(A, B, tid);   // only low half of F needed

    float2* yr = (float2*)(y + (size_t)b * LSEQ);
    const float sc = 1.0f / 8192.0f;
    #pragma unroll
    for (int it = 0; it < 8; it++) {
        int j = tid + it * NT;
        float2 f = B[PD(j)];
        yr[j] = make_float2(f.x * sc, -f.y * sc);
    }
}

// ---------------- launch ----------------
extern "C" void kernel_launch(void* const* d_in, const int* in_sizes, int n_in,
                              void* d_out, int out_size) {
    const float* x  = (const float*)d_in[0];
    const float* Bv = (const float*)d_in[1];
    const float* Cv = (const float*)d_in[2];
    float* y = (float*)d_out;
    (void)in_sizes; (void)n_in; (void)out_size;

    const int smem = 2 * PDSZ * (int)sizeof(float2);   // 147456 B
    cudaFuncSetAttribute(kprep_kernel, cudaFuncAttributeMaxDynamicSharedMemorySize, smem);
    cudaFuncSetAttribute(conv_kernel,  cudaFuncAttributeMaxDynamicSharedMemorySize, smem);

    setup_kernel<<<4353, 64>>>(Bv, Cv);
    kprep_kernel<<<1, NT, smem>>>();
    conv_kernel<<<NBATCH, NT, smem>>>(x, y);
}

// round 10
// speedup vs baseline: 1.3126x; 1.3126x over previous
#include <cuda_runtime.h>
#include <math.h>

#define LSEQ   8192
#define NBATCH 1024
#define NT     512
#define NSTATE 64
#define PI_F 3.14159265358979323846f

// -2*pi/8192 and -2*pi/16384 (twiddle angle steps)
#define ANG8K  (-7.66990393942820614e-4f)
#define ANG16K (-3.83495196971410307e-4f)

__device__ float2 g_wm[16384];   // WM[k] = exp(-2*pi*i*k/16384)  (kprep only)
__device__ float2 g_kh[4100];    // K_hat spectrum bins 0..4096
__device__ float2 g_kf[8200];    // rfft_16384 of padded K, bins 0..8192

// ---------------- complex helpers ----------------
static __device__ __forceinline__ float2 cmul(float2 a, float2 b) {
    return make_float2(a.x*b.x - a.y*b.y, a.x*b.y + a.y*b.x);
}
static __device__ __forceinline__ float2 cadd(float2 a, float2 b){ return make_float2(a.x+b.x, a.y+b.y); }
static __device__ __forceinline__ float2 csub(float2 a, float2 b){ return make_float2(a.x-b.x, a.y-b.y); }
static __device__ __forceinline__ float2 cconj(float2 a){ return make_float2(a.x, -a.y); }
static __device__ __forceinline__ float2 cscale(float2 a, float s){ return make_float2(a.x*s, a.y*s); }

// ---------------- merged setup (ALL fp32) ----------------
__global__ void setup_kernel(const float* __restrict__ Bv, const float* __restrict__ Cv) {
    if (blockIdx.x > 4096) {
        int k = (blockIdx.x - 4097) * 64 + threadIdx.x;   // 0..16383
        float s, c;
        sincospif((float)k / 8192.0f, &s, &c);
        g_wm[k] = make_float2(c, -s);
        return;
    }
    __shared__ float shg[5];
    __shared__ float wsum[2][8];
    int f = blockIdx.x;              // 0..4096
    int n = threadIdx.x;             // 0..63
    if (n == 0) {
        // sincosf (fp32): sin(float(pi)) ~ -8.74e-8 != 0 -> no Nyquist NaN.
        float th = (2.0f * PI_F / 8192.0f) * (float)f;
        float s, c;
        sincosf(th, &s, &c);
        float nr = 1.0f - c, ni = -s;
        float dr = 1.0f + c, di = s;
        float dd = dr*dr + di*di;
        shg[0] = 20.0f * (nr*dr + ni*di) / dd;
        shg[1] = 20.0f * (ni*dr - nr*di) / dd;
        shg[2] = dr; shg[3] = di; shg[4] = dd;
    }
    __syncthreads();
    float gr = shg[0], gi = shg[1];
    float er = gr + 0.5f;
    float ei = gi - PI_F * (float)n;
    float inv = 1.0f / (er*er + ei*ei);
    float ir =  er * inv, ii = -ei * inv;
    float b0 = Bv[n];
    float a0 = Cv[n];
    float p2 = (float)n + 0.5f;
    float p  = sqrtf(p2);
    float v00 = a0*b0, v01 = a0*p, v10 = p*b0, v11 = p2;
    float acc[8] = { v00*ir, v00*ii, v01*ir, v01*ii,
                     v10*ir, v10*ii, v11*ir, v11*ii };
    #pragma unroll
    for (int off = 16; off; off >>= 1) {
        #pragma unroll
        for (int t = 0; t < 8; t++)
            acc[t] += __shfl_down_sync(0xffffffffu, acc[t], off);
    }
    if ((n & 31) == 0) {
        #pragma unroll
        for (int t = 0; t < 8; t++) wsum[n >> 5][t] = acc[t];
    }
    __syncthreads();
    if (n == 0) {
        float k00r = wsum[0][0]+wsum[1][0], k00i = wsum[0][1]+wsum[1][1];
        float k01r = wsum[0][2]+wsum[1][2], k01i = wsum[0][3]+wsum[1][3];
        float k10r = wsum[0][4]+wsum[1][4], k10i = wsum[0][5]+wsum[1][5];
        float k11r = wsum[0][6]+wsum[1][6], k11i = wsum[0][7]+wsum[1][7];
        float ur = 1.0f + k11r, ui = k11i;
        float t1r = k01r*ur - k01i*ui, t1i = k01r*ui + k01i*ur;
        float t2r = t1r*k10r - t1i*k10i, t2i = t1r*k10i + t1i*k10r;
        float hr = k00r - t2r, hi = k00i - t2i;
        float dr = shg[2], di = shg[3], dd = shg[4];
        float c2r = 2.0f*dr/dd, c2i = -2.0f*di/dd;
        g_kh[f] = make_float2(c2r*hr - c2i*hi, c2r*hi + c2i*hr);
    }
}

// ---------------- DFT8 butterfly + twiddled scatter (shared by all stages) ----------------
static __device__ __forceinline__ void dft8_store(
    float2 x0, float2 x1, float2 x2, float2 x3,
    float2 x4, float2 x5, float2 x6, float2 x7,
    float2* dst, int o, int s, int ps /* p<<LS */) {
    float2 ea = cadd(x0, x4), em = csub(x0, x4);
    float2 eb = cadd(x2, x6), en = csub(x2, x6);
    float2 ej = make_float2(-en.y, en.x);
    float2 E0 = cadd(ea, eb), E1 = csub(em, ej);
    float2 E2 = csub(ea, eb), E3 = cadd(em, ej);
    float2 oa = cadd(x1, x5), om = csub(x1, x5);
    float2 ob = cadd(x3, x7), on = csub(x3, x7);
    float2 oj = make_float2(-on.y, on.x);
    float2 O0 = cadd(oa, ob), O1 = csub(om, oj);
    float2 O2 = csub(oa, ob), O3 = cadd(om, oj);
    const float C = 0.70710678118654752440f;
    float2 t0 = O0;
    float2 t1 = make_float2(C*(O1.x + O1.y), C*(O1.y - O1.x));   // w8^1*O1
    float2 t2 = make_float2(O2.y, -O2.x);                         // -i*O2
    float2 t3 = make_float2(C*(O3.y - O3.x), -C*(O3.x + O3.y));   // w8^3*O3
    float2 X0 = cadd(E0, t0), X4 = csub(E0, t0);
    float2 X1 = cadd(E1, t1), X5 = csub(E1, t1);
    float2 X2 = cadd(E2, t2), X6 = csub(E2, t2);
    float2 X3 = cadd(E3, t3), X7 = csub(E3, t3);
    // w1 = exp(-2*pi*i*ps/8192) via MUFU (|ang| < 0.79 rad -> accurate)
    float sn, cs;
    __sincosf((float)ps * ANG8K, &sn, &cs);
    float2 w1 = make_float2(cs, sn);
    float2 w2 = cmul(w1, w1);
    float2 w3 = cmul(w2, w1);
    float2 w4 = cmul(w2, w2);
    float2 w5 = cmul(w3, w2);
    float2 w6 = cmul(w3, w3);
    float2 w7 = cmul(w4, w3);
    dst[o]       = X0;
    dst[o + s]   = cmul(w1, X1);
    dst[o + 2*s] = cmul(w2, X2);
    dst[o + 3*s] = cmul(w3, X3);
    dst[o + 4*s] = cmul(w4, X4);
    dst[o + 5*s] = cmul(w5, X5);
    dst[o + 6*s] = cmul(w6, X6);
    dst[o + 7*s] = cmul(w7, X7);
}

// radix-8 stage over smem, log2(s) = LS. Trailing sync.
template<int LS>
static __device__ __forceinline__ void stage8(const float2* __restrict__ src,
                                              float2* __restrict__ dst, int tid) {
    const int s = 1 << LS;
    #pragma unroll
    for (int it = 0; it < 2; it++) {
        int idx = tid + it * NT;          // < 1024
        int p = idx >> LS;
        int q = idx & (s - 1);
        float2 x0 = src[idx];
        float2 x1 = src[idx + 1024];
        float2 x2 = src[idx + 2048];
        float2 x3 = src[idx + 3072];
        float2 x4 = src[idx + 4096];
        float2 x5 = src[idx + 5120];
        float2 x6 = src[idx + 6144];
        float2 x7 = src[idx + 7168];
        dft8_store(x0,x1,x2,x3,x4,x5,x6,x7, dst, q + (p << (LS + 3)), s, p << LS);
    }
    __syncthreads();
}

// stage 0 reading input directly from gmem (upper half implicitly zero). Trailing sync.
static __device__ __forceinline__ void stage0_gmem(const float2* __restrict__ xr,
                                                   float2* __restrict__ dst, int tid) {
    const float2 Z = make_float2(0.f, 0.f);
    #pragma unroll
    for (int it = 0; it < 2; it++) {
        int p = tid + it * NT;            // idx = p, s=1, q=0
        float2 x0 = xr[p];
        float2 x1 = xr[p + 1024];
        float2 x2 = xr[p + 2048];
        float2 x3 = xr[p + 3072];
        dft8_store(x0,x1,x2,x3, Z,Z,Z,Z, dst, p << 3, 1, p);
    }
    __syncthreads();
}

// ---------------- kprep's full FFT (table twiddles; validated R8 path) ----------------
template<int NTH, bool ZHI, bool SKIPHI>
static __device__ __forceinline__ void fft8192_r8(float2* A, float2* B, int tid) {
    float2* src = A;
    float2* dst = B;
    #pragma unroll
    for (int st = 0; st < 4; st++) {
        const int ls = 3 * st;
        const int s  = 1 << ls;
        #pragma unroll
        for (int it = 0; it < 1024 / NTH; it++) {
            int idx = tid + it * NTH;
            int p = idx >> ls;
            int q = idx & (s - 1);
            float2 x0 = src[idx];
            float2 x1 = src[idx + 1024];
            float2 x2 = src[idx + 2048];
            float2 x3 = src[idx + 3072];
            float2 x4, x5, x6, x7;
            if (ZHI && st == 0) {
                x4 = x5 = x6 = x7 = make_float2(0.f, 0.f);
            } else {
                x4 = src[idx + 4096];
                x5 = src[idx + 5120];
                x6 = src[idx + 6144];
                x7 = src[idx + 7168];
            }
            float2 ea = cadd(x0, x4), em = csub(x0, x4);
            float2 eb = cadd(x2, x6), en = csub(x2, x6);
            float2 ej = make_float2(-en.y, en.x);
            float2 E0 = cadd(ea, eb), E1 = csub(em, ej);
            float2 E2 = csub(ea, eb), E3 = cadd(em, ej);
            float2 oa = cadd(x1, x5), om = csub(x1, x5);
            float2 ob = cadd(x3, x7), on = csub(x3, x7);
            float2 oj = make_float2(-on.y, on.x);
            float2 O0 = cadd(oa, ob), O1 = csub(om, oj);
            float2 O2 = csub(oa, ob), O3 = cadd(om, oj);
            const float C = 0.70710678118654752440f;
            float2 t0 = O0;
            float2 t1 = make_float2(C*(O1.x + O1.y), C*(O1.y - O1.x));
            float2 t2 = make_float2(O2.y, -O2.x);
            float2 t3 = make_float2(C*(O3.y - O3.x), -C*(O3.x + O3.y));
            float2 X0 = cadd(E0, t0), X4 = csub(E0, t0);
            float2 X1 = cadd(E1, t1), X5 = csub(E1, t1);
            float2 X2 = cadd(E2, t2), X6 = csub(E2, t2);
            float2 X3 = cadd(E3, t3), X7 = csub(E3, t3);
            int tw = (p << (ls + 1));
            float2 w1 = g_wm[tw];
            float2 w2 = cmul(w1, w1);
            float2 w3 = cmul(w2, w1);
            float2 w4 = cmul(w2, w2);
            float2 w5 = cmul(w3, w2);
            float2 w6 = cmul(w3, w3);
            float2 w7 = cmul(w4, w3);
            int o = q + (p << (ls + 3));
            dst[o]         = X0;
            dst[o + s]     = cmul(w1, X1);
            dst[o + 2*s]   = cmul(w2, X2);
            dst[o + 3*s]   = cmul(w3, X3);
            dst[o + 4*s]   = cmul(w4, X4);
            dst[o + 5*s]   = cmul(w5, X5);
            dst[o + 6*s]   = cmul(w6, X6);
            dst[o + 7*s]   = cmul(w7, X7);
        }
        __syncthreads();
        float2* t = src; src = dst; dst = t;
    }
    #pragma unroll
    for (int it = 0; it < 4096 / NTH; it++) {
        int q = tid + it * NTH;
        float2 a = src[q], b = src[q + 4096];
        dst[q] = cadd(a, b);
        if (!SKIPHI) dst[q + 4096] = csub(a, b);
    }
    __syncthreads();
}

// ---------------- K preparation (R8-validated) ----------------
__global__ void kprep_kernel() {
    extern __shared__ float2 sm[];
    float2* A = sm;
    float2* B = sm + 8192;
    int tid = threadIdx.x;

    #pragma unroll
    for (int it = 0; it < 16; it++) {
        int f = tid + it * NT;
        float2 kh = (f <= 4096) ? g_kh[f] : g_kh[8192 - f];
        A[f] = (f <= 4096) ? cconj(kh) : kh;
    }
    __syncthreads();
    fft8192_r8<NT, false, false>(A, B, tid);
    const float sc = 1.0f / 8192.0f;
    #pragma unroll
    for (int it = 0; it < 8; it++) {
        int j = tid + it * NT;
        A[j] = make_float2(B[2*j].x * sc, B[2*j + 1].x * sc);
    }
    __syncthreads();
    fft8192_r8<NT, true, false>(A, B, tid);
    for (int k = tid; k <= 4096; k += NT) {
        if (k == 0) {
            float2 Z0 = B[0];
            g_kf[0]    = make_float2(Z0.x + Z0.y, 0.f);
            g_kf[8192] = make_float2(Z0.x - Z0.y, 0.f);
        } else {
            int hk = 8192 - k;
            float2 Zk  = B[k];
            float2 Zhc = cconj(B[hk]);
            float2 E  = cscale(cadd(Zk, Zhc), 0.5f);
            float2 Om = csub(Zk, Zhc);
            float2 O  = make_float2(0.5f * Om.y, -0.5f * Om.x);
            float2 w  = g_wm[k];
            g_kf[k] = cadd(E, cmul(w, O));
            if (k != 4096) {
                float2 wh = make_float2(-w.x, w.y);
                g_kf[hk] = cadd(cconj(E), cmul(wh, cconj(O)));
            }
        }
    }
}

// ---------------- main batched FFT convolution ----------------
// FFT1: gmem->A, A->B, B->A, A->B (pre-radix-2 result P in B).
// Pointwise fuses FFT1's final radix-2 (reads P) and writes IFFT input to A.
// IFFT: A->B, B->A, A->B, B->A (pre-radix-2 result in A).
// Output fuses IFFT's final radix-2.
__global__ void __launch_bounds__(NT, 1) conv_kernel(const float* __restrict__ x,
                                                     float* __restrict__ y) {
    extern __shared__ float2 sm[];
    float2* A = sm;
    float2* B = sm + 8192;
    int b = blockIdx.x;
    int tid = threadIdx.x;

    const float2* xr = (const float2*)(x + (size_t)b * LSEQ);

    // FFT1 (input upper half implicitly zero)
    stage0_gmem(xr, A, tid);
    stage8<3>(A, B, tid);
    stage8<6>(B, A, tid);
    stage8<9>(A, B, tid);   // P in B (pre final radix-2)

    // pointwise: fused radix-2 read of P, multiply by Kf, repack conj(Zy) into A
    for (int k = tid; k <= 4096; k += NT) {
        if (k == 0) {
            float2 Z0 = cadd(B[0], B[4096]);          // radix-2 low bin 0
            float X0 = Z0.x + Z0.y;
            float XH = Z0.x - Z0.y;
            float2 Y0 = cscale(g_kf[0], X0);
            float2 YH = cscale(g_kf[8192], XH);
            float2 Yhc = cconj(YH);
            float2 S = cscale(cadd(Y0, Yhc), 0.5f);
            float2 D = cscale(csub(Y0, Yhc), 0.5f);
            float2 Zy0 = make_float2(S.x - D.y, S.y + D.x);
            A[0] = cconj(Zy0);
        } else {
            int hk = 8192 - k;
            // fused radix-2: Z[k] (k<=4096) and Z[hk] (hk>=4096)
            float2 Zk  = (k < 4096) ? cadd(B[k], B[k + 4096])
                                    : csub(B[0], B[4096]);          // k == 4096
            float2 Zh  = (k < 4096) ? csub(B[4096 - k], B[8192 - k])
                                    : Zk;                            // hk == k == 4096
            float2 Zhc = cconj(Zh);
            float2 E  = cscale(cadd(Zk, Zhc), 0.5f);
            float2 Om = csub(Zk, Zhc);
            float2 O  = make_float2(0.5f * Om.y, -0.5f * Om.x);
            // w = exp(-2*pi*i*k/16384) via MUFU (|ang| <= pi/2)
            float sn, cs;
            __sincosf((float)k * ANG16K, &sn, &cs);
            float2 w = make_float2(cs, sn);
            float2 Xk = cadd(E, cmul(w, O));
            float2 wh = make_float2(-w.x, w.y);                      // WM[hk] = -conj(w)
            float2 Xh = cadd(cconj(E), cmul(wh, cconj(O)));
            float2 Yk = cmul(Xk, g_kf[k]);
            float2 Yh = cmul(Xh, g_kf[hk]);
            float2 Yhc = cconj(Yh);
            float2 S = cscale(cadd(Yk, Yhc), 0.5f);
            float2 D = cscale(csub(Yk, Yhc), 0.5f);
            float2 u = cmul(cconj(w), D);
            float2 Zyk = make_float2(S.x - u.y, S.y + u.x);
            A[k] = cconj(Zyk);
            if (k != 4096) {
                float2 Ykc = cconj(Yk);
                float2 S2 = cscale(cadd(Yh, Ykc), 0.5f);
                float2 D2 = cscale(csub(Yh, Ykc), 0.5f);
                float2 v = cmul(w, D2);
                float2 Zyh = make_float2(S2.x + v.y, S2.y - v.x);
                A[hk] = cconj(Zyh);
            }
        }
    }
    __syncthreads();

    // IFFT (conj trick; input conj(Zy) in A)
    stage8<0>(A, B, tid);
    stage8<3>(B, A, tid);
    stage8<6>(A, B, tid);
    stage8<9>(B, A, tid);   // pre-radix-2 result in A

    // output: fused final radix-2 (low half only) + conj + scale
    float2* yr = (float2*)(y + (size_t)b * LSEQ);
    const float sc = 1.0f / 8192.0f;
    #pragma unroll
    for (int it = 0; it < 8; it++) {
        int j = tid + it * NT;          // j < 4096
        float2 f = cadd(A[j], A[j + 4096]);
        yr[j] = make_float2(f.x * sc, -f.y * sc);
    }
}

// ---------------- launch ----------------
extern "C" void kernel_launch(void* const* d_in, const int* in_sizes, int n_in,
                              void* d_out, int out_size) {
    const float* x  = (const float*)d_in[0];
    const float* Bv = (const float*)d_in[1];
    const float* Cv = (const float*)d_in[2];
    float* y = (float*)d_out;
    (void)in_sizes; (void)n_in; (void)out_size;

    const int smem = 2 * 8192 * (int)sizeof(float2);   // 131072 B
    cudaFuncSetAttribute(kprep_kernel, cudaFuncAttributeMaxDynamicSharedMemorySize, smem);
    cudaFuncSetAttribute(conv_kernel,  cudaFuncAttributeMaxDynamicSharedMemorySize, smem);

    setup_kernel<<<4353, 64>>>(Bv, Cv);
    kprep_kernel<<<1, NT, smem>>>();
    conv_kernel<<<NBATCH, NT, smem>>>(x, y);
}

// round 11
// speedup vs baseline: 1.4081x; 1.0728x over previous
#include <cuda_runtime.h>
#include <math.h>

#define LSEQ   8192
#define NBATCH 1024
#define NT     512
#define NSTATE 64
#define PI_F 3.14159265358979323846f

// -2*pi/8192 and -2*pi/16384 (twiddle angle steps)
#define ANG8K  (-7.66990393942820614e-4f)
#define ANG16K (-3.83495196971410307e-4f)

__device__ float2 g_wm[16384];   // WM[k] = exp(-2*pi*i*k/16384)  (kprep only)
__device__ float2 g_kh[4100];    // K_hat spectrum bins 0..4096
__device__ float2 g_kf[8200];    // rfft_16384 of padded K, bins 0..8192

// ---------------- complex helpers ----------------
static __device__ __forceinline__ float2 cmul(float2 a, float2 b) {
    return make_float2(a.x*b.x - a.y*b.y, a.x*b.y + a.y*b.x);
}
static __device__ __forceinline__ float2 cadd(float2 a, float2 b){ return make_float2(a.x+b.x, a.y+b.y); }
static __device__ __forceinline__ float2 csub(float2 a, float2 b){ return make_float2(a.x-b.x, a.y-b.y); }
static __device__ __forceinline__ float2 cconj(float2 a){ return make_float2(a.x, -a.y); }
static __device__ __forceinline__ float2 cscale(float2 a, float s){ return make_float2(a.x*s, a.y*s); }

// Per-pass smem address swizzles (bijective, GF(2)-linear):
// T1 kills st0's 8-way store conflict; T2 kills st1's 2-way store conflict.
// Linear (consecutive-per-lane) reads under T1/T2 stay conflict-free.
template<int SW>
static __device__ __forceinline__ int swz(int i) {
    if (SW == 1) return i ^ ((i >> 3) & 15);
    if (SW == 2) return i ^ (((i >> 6) & 7) << 3);
    return i;
}

// ---------------- merged setup (ALL fp32) ----------------
__global__ void setup_kernel(const float* __restrict__ Bv, const float* __restrict__ Cv) {
    if (blockIdx.x > 4096) {
        int k = (blockIdx.x - 4097) * 64 + threadIdx.x;   // 0..16383
        float s, c;
        sincospif((float)k / 8192.0f, &s, &c);
        g_wm[k] = make_float2(c, -s);
        return;
    }
    __shared__ float shg[5];
    __shared__ float wsum[2][8];
    int f = blockIdx.x;              // 0..4096
    int n = threadIdx.x;             // 0..63
    if (n == 0) {
        // sincosf (fp32): sin(float(pi)) ~ -8.74e-8 != 0 -> no Nyquist NaN.
        float th = (2.0f * PI_F / 8192.0f) * (float)f;
        float s, c;
        sincosf(th, &s, &c);
        float nr = 1.0f - c, ni = -s;
        float dr = 1.0f + c, di = s;
        float dd = dr*dr + di*di;
        shg[0] = 20.0f * (nr*dr + ni*di) / dd;
        shg[1] = 20.0f * (ni*dr - nr*di) / dd;
        shg[2] = dr; shg[3] = di; shg[4] = dd;
    }
    __syncthreads();
    float gr = shg[0], gi = shg[1];
    float er = gr + 0.5f;
    float ei = gi - PI_F * (float)n;
    float inv = 1.0f / (er*er + ei*ei);
    float ir =  er * inv, ii = -ei * inv;
    float b0 = Bv[n];
    float a0 = Cv[n];
    float p2 = (float)n + 0.5f;
    float p  = sqrtf(p2);
    float v00 = a0*b0, v01 = a0*p, v10 = p*b0, v11 = p2;
    float acc[8] = { v00*ir, v00*ii, v01*ir, v01*ii,
                     v10*ir, v10*ii, v11*ir, v11*ii };
    #pragma unroll
    for (int off = 16; off; off >>= 1) {
        #pragma unroll
        for (int t = 0; t < 8; t++)
            acc[t] += __shfl_down_sync(0xffffffffu, acc[t], off);
    }
    if ((n & 31) == 0) {
        #pragma unroll
        for (int t = 0; t < 8; t++) wsum[n >> 5][t] = acc[t];
    }
    __syncthreads();
    if (n == 0) {
        float k00r = wsum[0][0]+wsum[1][0], k00i = wsum[0][1]+wsum[1][1];
        float k01r = wsum[0][2]+wsum[1][2], k01i = wsum[0][3]+wsum[1][3];
        float k10r = wsum[0][4]+wsum[1][4], k10i = wsum[0][5]+wsum[1][5];
        float k11r = wsum[0][6]+wsum[1][6], k11i = wsum[0][7]+wsum[1][7];
        float ur = 1.0f + k11r, ui = k11i;
        float t1r = k01r*ur - k01i*ui, t1i = k01r*ui + k01i*ur;
        float t2r = t1r*k10r - t1i*k10i, t2i = t1r*k10i + t1i*k10r;
        float hr = k00r - t2r, hi = k00i - t2i;
        float dr = shg[2], di = shg[3], dd = shg[4];
        float c2r = 2.0f*dr/dd, c2i = -2.0f*di/dd;
        g_kh[f] = make_float2(c2r*hr - c2i*hi, c2r*hi + c2i*hr);
    }
}

// ---------------- DFT8 butterfly + twiddled scatter ----------------
template<int SWD>
static __device__ __forceinline__ void dft8_store(
    float2 x0, float2 x1, float2 x2, float2 x3,
    float2 x4, float2 x5, float2 x6, float2 x7,
    float2* dst, int o, int s, int ps /* p*s */) {
    float2 ea = cadd(x0, x4), em = csub(x0, x4);
    float2 eb = cadd(x2, x6), en = csub(x2, x6);
    float2 ej = make_float2(-en.y, en.x);
    float2 E0 = cadd(ea, eb), E1 = csub(em, ej);
    float2 E2 = csub(ea, eb), E3 = cadd(em, ej);
    float2 oa = cadd(x1, x5), om = csub(x1, x5);
    float2 ob = cadd(x3, x7), on = csub(x3, x7);
    float2 oj = make_float2(-on.y, on.x);
    float2 O0 = cadd(oa, ob), O1 = csub(om, oj);
    float2 O2 = csub(oa, ob), O3 = cadd(om, oj);
    const float C = 0.70710678118654752440f;
    float2 t0 = O0;
    float2 t1 = make_float2(C*(O1.x + O1.y), C*(O1.y - O1.x));   // w8^1*O1
    float2 t2 = make_float2(O2.y, -O2.x);                         // -i*O2
    float2 t3 = make_float2(C*(O3.y - O3.x), -C*(O3.x + O3.y));   // w8^3*O3
    float2 X0 = cadd(E0, t0), X4 = csub(E0, t0);
    float2 X1 = cadd(E1, t1), X5 = csub(E1, t1);
    float2 X2 = cadd(E2, t2), X6 = csub(E2, t2);
    float2 X3 = cadd(E3, t3), X7 = csub(E3, t3);
    float sn, cs;
    __sincosf((float)ps * ANG8K, &sn, &cs);
    float2 w1 = make_float2(cs, sn);
    float2 w2 = cmul(w1, w1);
    float2 w3 = cmul(w2, w1);
    float2 w4 = cmul(w2, w2);
    float2 w5 = cmul(w3, w2);
    float2 w6 = cmul(w3, w3);
    float2 w7 = cmul(w4, w3);
    dst[swz<SWD>(o)]       = X0;
    dst[swz<SWD>(o + s)]   = cmul(w1, X1);
    dst[swz<SWD>(o + 2*s)] = cmul(w2, X2);
    dst[swz<SWD>(o + 3*s)] = cmul(w3, X3);
    dst[swz<SWD>(o + 4*s)] = cmul(w4, X4);
    dst[swz<SWD>(o + 5*s)] = cmul(w5, X5);
    dst[swz<SWD>(o + 6*s)] = cmul(w6, X6);
    dst[swz<SWD>(o + 7*s)] = cmul(w7, X7);
}

// radix-8 stage over smem, log2(s) = LS; SWS/SWD = src/dst swizzle ids. Trailing sync.
template<int LS, int SWS, int SWD>
static __device__ __forceinline__ void stage8(const float2* __restrict__ src,
                                              float2* __restrict__ dst, int tid) {
    const int s = 1 << LS;
    #pragma unroll
    for (int it = 0; it < 2; it++) {
        int idx = tid + it * NT;          // < 1024
        int p = idx >> LS;
        int q = idx & (s - 1);
        float2 x0 = src[swz<SWS>(idx)];
        float2 x1 = src[swz<SWS>(idx + 1024)];
        float2 x2 = src[swz<SWS>(idx + 2048)];
        float2 x3 = src[swz<SWS>(idx + 3072)];
        float2 x4 = src[swz<SWS>(idx + 4096)];
        float2 x5 = src[swz<SWS>(idx + 5120)];
        float2 x6 = src[swz<SWS>(idx + 6144)];
        float2 x7 = src[swz<SWS>(idx + 7168)];
        dft8_store<SWD>(x0,x1,x2,x3,x4,x5,x6,x7, dst, q + (p << (LS + 3)), s, p << LS);
    }
    __syncthreads();
}

// stage 0 reading input from gmem (upper half implicitly zero); writes T1. Trailing sync.
static __device__ __forceinline__ void stage0_gmem(const float2* __restrict__ xr,
                                                   float2* __restrict__ dst, int tid) {
    const float2 Z = make_float2(0.f, 0.f);
    #pragma unroll
    for (int it = 0; it < 2; it++) {
        int p = tid + it * NT;            // idx = p, s=1, q=0
        float2 x0 = xr[p];
        float2 x1 = xr[p + 1024];
        float2 x2 = xr[p + 2048];
        float2 x3 = xr[p + 3072];
        dft8_store<1>(x0,x1,x2,x3, Z,Z,Z,Z, dst, p << 3, 1, p);
    }
    __syncthreads();
}

// ---------------- kprep's full FFT (table twiddles; validated, unswizzled) ----------------
template<int NTH, bool ZHI, bool SKIPHI>
static __device__ __forceinline__ void fft8192_r8(float2* A, float2* B, int tid) {
    float2* src = A;
    float2* dst = B;
    #pragma unroll
    for (int st = 0; st < 4; st++) {
        const int ls = 3 * st;
        const int s  = 1 << ls;
        #pragma unroll
        for (int it = 0; it < 1024 / NTH; it++) {
            int idx = tid + it * NTH;
            int p = idx >> ls;
            int q = idx & (s - 1);
            float2 x0 = src[idx];
            float2 x1 = src[idx + 1024];
            float2 x2 = src[idx + 2048];
            float2 x3 = src[idx + 3072];
            float2 x4, x5, x6, x7;
            if (ZHI && st == 0) {
                x4 = x5 = x6 = x7 = make_float2(0.f, 0.f);
            } else {
                x4 = src[idx + 4096];
                x5 = src[idx + 5120];
                x6 = src[idx + 6144];
                x7 = src[idx + 7168];
            }
            float2 ea = cadd(x0, x4), em = csub(x0, x4);
            float2 eb = cadd(x2, x6), en = csub(x2, x6);
            float2 ej = make_float2(-en.y, en.x);
            float2 E0 = cadd(ea, eb), E1 = csub(em, ej);
            float2 E2 = csub(ea, eb), E3 = cadd(em, ej);
            float2 oa = cadd(x1, x5), om = csub(x1, x5);
            float2 ob = cadd(x3, x7), on = csub(x3, x7);
            float2 oj = make_float2(-on.y, on.x);
            float2 O0 = cadd(oa, ob), O1 = csub(om, oj);
            float2 O2 = csub(oa, ob), O3 = cadd(om, oj);
            const float C = 0.70710678118654752440f;
            float2 t0 = O0;
            float2 t1 = make_float2(C*(O1.x + O1.y), C*(O1.y - O1.x));
            float2 t2 = make_float2(O2.y, -O2.x);
            float2 t3 = make_float2(C*(O3.y - O3.x), -C*(O3.x + O3.y));
            float2 X0 = cadd(E0, t0), X4 = csub(E0, t0);
            float2 X1 = cadd(E1, t1), X5 = csub(E1, t1);
            float2 X2 = cadd(E2, t2), X6 = csub(E2, t2);
            float2 X3 = cadd(E3, t3), X7 = csub(E3, t3);
            int tw = (p << (ls + 1));
            float2 w1 = g_wm[tw];
            float2 w2 = cmul(w1, w1);
            float2 w3 = cmul(w2, w1);
            float2 w4 = cmul(w2, w2);
            float2 w5 = cmul(w3, w2);
            float2 w6 = cmul(w3, w3);
            float2 w7 = cmul(w4, w3);
            int o = q + (p << (ls + 3));
            dst[o]         = X0;
            dst[o + s]     = cmul(w1, X1);
            dst[o + 2*s]   = cmul(w2, X2);
            dst[o + 3*s]   = cmul(w3, X3);
            dst[o + 4*s]   = cmul(w4, X4);
            dst[o + 5*s]   = cmul(w5, X5);
            dst[o + 6*s]   = cmul(w6, X6);
            dst[o + 7*s]   = cmul(w7, X7);
        }
        __syncthreads();
        float2* t = src; src = dst; dst = t;
    }
    #pragma unroll
    for (int it = 0; it < 4096 / NTH; it++) {
        int q = tid + it * NTH;
        float2 a = src[q], b = src[q + 4096];
        dst[q] = cadd(a, b);
        if (!SKIPHI) dst[q + 4096] = csub(a, b);
    }
    __syncthreads();
}

// ---------------- K preparation (validated) ----------------
__global__ void kprep_kernel() {
    extern __shared__ float2 sm[];
    float2* A = sm;
    float2* B = sm + 8192;
    int tid = threadIdx.x;

    #pragma unroll
    for (int it = 0; it < 16; it++) {
        int f = tid + it * NT;
        float2 kh = (f <= 4096) ? g_kh[f] : g_kh[8192 - f];
        A[f] = (f <= 4096) ? cconj(kh) : kh;
    }
    __syncthreads();
    fft8192_r8<NT, false, false>(A, B, tid);
    const float sc = 1.0f / 8192.0f;
    #pragma unroll
    for (int it = 0; it < 8; it++) {
        int j = tid + it * NT;
        A[j] = make_float2(B[2*j].x * sc, B[2*j + 1].x * sc);
    }
    __syncthreads();
    fft8192_r8<NT, true, false>(A, B, tid);
    for (int k = tid; k <= 4096; k += NT) {
        if (k == 0) {
            float2 Z0 = B[0];
            g_kf[0]    = make_float2(Z0.x + Z0.y, 0.f);
            g_kf[8192] = make_float2(Z0.x - Z0.y, 0.f);
        } else {
            int hk = 8192 - k;
            float2 Zk  = B[k];
            float2 Zhc = cconj(B[hk]);
            float2 E  = cscale(cadd(Zk, Zhc), 0.5f);
            float2 Om = csub(Zk, Zhc);
            float2 O  = make_float2(0.5f * Om.y, -0.5f * Om.x);
            float2 w  = g_wm[k];
            g_kf[k] = cadd(E, cmul(w, O));
            if (k != 4096) {
                float2 wh = make_float2(-w.x, w.y);
                g_kf[hk] = cadd(cconj(E), cmul(wh, cconj(O)));
            }
        }
    }
}

// ---------------- main batched FFT convolution ----------------
// FFT1: gmem->A(T1), A(T1)->B(T2), B(T2)->A, A->B (pre-radix-2 P in B, plain).
// Pointwise fuses FFT1's final radix-2 (reads B plain) and writes A plain.
// IFFT: A->B(T1), B(T1)->A(T2), A(T2)->B, B->A (pre-radix-2 in A, plain).
// Output fuses IFFT's final radix-2.
__global__ void __launch_bounds__(NT, 1) conv_kernel(const float* __restrict__ x,
                                                     float* __restrict__ y) {
    extern __shared__ float2 sm[];
    float2* A = sm;
    float2* B = sm + 8192;
    int b = blockIdx.x;
    int tid = threadIdx.x;

    const float2* xr = (const float2*)(x + (size_t)b * LSEQ);

    // FFT1 (input upper half implicitly zero)
    stage0_gmem(xr, A, tid);          // -> A (T1)
    stage8<3, 1, 2>(A, B, tid);       // -> B (T2)
    stage8<6, 2, 0>(B, A, tid);       // -> A (plain)
    stage8<9, 0, 0>(A, B, tid);       // -> B = P (pre final radix-2, plain)

    // pointwise: fused radix-2 read of P, multiply by Kf, repack conj(Zy) into A
    for (int k = tid; k <= 4096; k += NT) {
        if (k == 0) {
            float2 Z0 = cadd(B[0], B[4096]);
            float X0 = Z0.x + Z0.y;
            float XH = Z0.x - Z0.y;
            float2 Y0 = cscale(g_kf[0], X0);
            float2 YH = cscale(g_kf[8192], XH);
            float2 Yhc = cconj(YH);
            float2 S = cscale(cadd(Y0, Yhc), 0.5f);
            float2 D = cscale(csub(Y0, Yhc), 0.5f);
            float2 Zy0 = make_float2(S.x - D.y, S.y + D.x);
            A[0] = cconj(Zy0);
        } else {
            int hk = 8192 - k;
            float2 Zk  = (k < 4096) ? cadd(B[k], B[k + 4096])
                                    : csub(B[0], B[4096]);
            float2 Zh  = (k < 4096) ? csub(B[4096 - k], B[8192 - k])
                                    : Zk;
            float2 Zhc = cconj(Zh);
            float2 E  = cscale(cadd(Zk, Zhc), 0.5f);
            float2 Om = csub(Zk, Zhc);
            float2 O  = make_float2(0.5f * Om.y, -0.5f * Om.x);
            float sn, cs;
            __sincosf((float)k * ANG16K, &sn, &cs);
            float2 w = make_float2(cs, sn);
            float2 Xk = cadd(E, cmul(w, O));
            float2 wh = make_float2(-w.x, w.y);
            float2 Xh = cadd(cconj(E), cmul(wh, cconj(O)));
            float2 Yk = cmul(Xk, g_kf[k]);
            float2 Yh = cmul(Xh, g_kf[hk]);
            float2 Yhc = cconj(Yh);
            float2 S = cscale(cadd(Yk, Yhc), 0.5f);
            float2 D = cscale(csub(Yk, Yhc), 0.5f);
            float2 u = cmul(cconj(w), D);
            float2 Zyk = make_float2(S.x - u.y, S.y + u.x);
            A[k] = cconj(Zyk);
            if (k != 4096) {
                float2 Ykc = cconj(Yk);
                float2 S2 = cscale(cadd(Yh, Ykc), 0.5f);
                float2 D2 = cscale(csub(Yh, Ykc), 0.5f);
                float2 v = cmul(w, D2);
                float2 Zyh = make_float2(S2.x + v.y, S2.y - v.x);
                A[hk] = cconj(Zyh);
            }
        }
    }
    __syncthreads();

    // IFFT (conj trick; input conj(Zy) in A, plain)
    stage8<0, 0, 1>(A, B, tid);       // -> B (T1)
    stage8<3, 1, 2>(B, A, tid);       // -> A (T2)
    stage8<6, 2, 0>(A, B, tid);       // -> B (plain)
    stage8<9, 0, 0>(B, A, tid);       // -> A (pre-radix-2, plain)

    // output: fused final radix-2 (low half only) + conj + scale
    float2* yr = (float2*)(y + (size_t)b * LSEQ);
    const float sc = 1.0f / 8192.0f;
    #pragma unroll
    for (int it = 0; it < 8; it++) {
        int j = tid + it * NT;
        float2 f = cadd(A[j], A[j + 4096]);
        yr[j] = make_float2(f.x * sc, -f.y * sc);
    }
}

// ---------------- launch ----------------
extern "C" void kernel_launch(void* const* d_in, const int* in_sizes, int n_in,
                              void* d_out, int out_size) {
    const float* x  = (const float*)d_in[0];
    const float* Bv = (const float*)d_in[1];
    const float* Cv = (const float*)d_in[2];
    float* y = (float*)d_out;
    (void)in_sizes; (void)n_in; (void)out_size;

    const int smem = 2 * 8192 * (int)sizeof(float2);   // 131072 B
    cudaFuncSetAttribute(kprep_kernel, cudaFuncAttributeMaxDynamicSharedMemorySize, smem);
    cudaFuncSetAttribute(conv_kernel,  cudaFuncAttributeMaxDynamicSharedMemorySize, smem);

    setup_kernel<<<4353, 64>>>(Bv, Cv);
    kprep_kernel<<<1, NT, smem>>>();
    conv_kernel<<<NBATCH, NT, smem>>>(x, y);
}

// round 12
// speedup vs baseline: 1.4793x; 1.0506x over previous
#include <cuda_runtime.h>
#include <math.h>

#define LSEQ   8192
#define NBATCH 1024
#define NT     512
#define NSTATE 64
#define PI_F 3.14159265358979323846f

// -2*pi/8192 and -2*pi/16384 (twiddle angle steps)
#define ANG8K  (-7.66990393942820614e-4f)
#define ANG16K (-3.83495196971410307e-4f)

__device__ float2 g_wm[16384];   // kprep only
__device__ float2 g_kh[4100];
__device__ float2 g_kf[8200];

// ---------------- complex helpers ----------------
static __device__ __forceinline__ float2 cmul(float2 a, float2 b) {
    return make_float2(a.x*b.x - a.y*b.y, a.x*b.y + a.y*b.x);
}
static __device__ __forceinline__ float2 cadd(float2 a, float2 b){ return make_float2(a.x+b.x, a.y+b.y); }
static __device__ __forceinline__ float2 csub(float2 a, float2 b){ return make_float2(a.x-b.x, a.y-b.y); }
static __device__ __forceinline__ float2 cconj(float2 a){ return make_float2(a.x, -a.y); }
static __device__ __forceinline__ float2 cscale(float2 a, float s){ return make_float2(a.x*s, a.y*s); }

// Per-pass smem swizzles (bijective): T1 kills st(s=1) 8-way store conflict,
// T2 kills st(s=8) 2-way store conflict; linear reads stay conflict-free.
template<int SW>
static __device__ __forceinline__ int swz(int i) {
    if (SW == 1) return i ^ ((i >> 3) & 15);
    if (SW == 2) return i ^ (((i >> 6) & 7) << 3);
    return i;
}

// ---------------- merged setup (ALL fp32) ----------------
__global__ void setup_kernel(const float* __restrict__ Bv, const float* __restrict__ Cv) {
    if (blockIdx.x > 4096) {
        int k = (blockIdx.x - 4097) * 64 + threadIdx.x;
        float s, c;
        sincospif((float)k / 8192.0f, &s, &c);
        g_wm[k] = make_float2(c, -s);
        return;
    }
    __shared__ float shg[5];
    __shared__ float wsum[2][8];
    int f = blockIdx.x;
    int n = threadIdx.x;
    if (n == 0) {
        float th = (2.0f * PI_F / 8192.0f) * (float)f;
        float s, c;
        sincosf(th, &s, &c);      // fp32: no exact zero at Nyquist -> no NaN
        float nr = 1.0f - c, ni = -s;
        float dr = 1.0f + c, di = s;
        float dd = dr*dr + di*di;
        shg[0] = 20.0f * (nr*dr + ni*di) / dd;
        shg[1] = 20.0f * (ni*dr - nr*di) / dd;
        shg[2] = dr; shg[3] = di; shg[4] = dd;
    }
    __syncthreads();
    float gr = shg[0], gi = shg[1];
    float er = gr + 0.5f;
    float ei = gi - PI_F * (float)n;
    float inv = 1.0f / (er*er + ei*ei);
    float ir =  er * inv, ii = -ei * inv;
    float b0 = Bv[n];
    float a0 = Cv[n];
    float p2 = (float)n + 0.5f;
    float p  = sqrtf(p2);
    float v00 = a0*b0, v01 = a0*p, v10 = p*b0, v11 = p2;
    float acc[8] = { v00*ir, v00*ii, v01*ir, v01*ii,
                     v10*ir, v10*ii, v11*ir, v11*ii };
    #pragma unroll
    for (int off = 16; off; off >>= 1) {
        #pragma unroll
        for (int t = 0; t < 8; t++)
            acc[t] += __shfl_down_sync(0xffffffffu, acc[t], off);
    }
    if ((n & 31) == 0) {
        #pragma unroll
        for (int t = 0; t < 8; t++) wsum[n >> 5][t] = acc[t];
    }
    __syncthreads();
    if (n == 0) {
        float k00r = wsum[0][0]+wsum[1][0], k00i = wsum[0][1]+wsum[1][1];
        float k01r = wsum[0][2]+wsum[1][2], k01i = wsum[0][3]+wsum[1][3];
        float k10r = wsum[0][4]+wsum[1][4], k10i = wsum[0][5]+wsum[1][5];
        float k11r = wsum[0][6]+wsum[1][6], k11i = wsum[0][7]+wsum[1][7];
        float ur = 1.0f + k11r, ui = k11i;
        float t1r = k01r*ur - k01i*ui, t1i = k01r*ui + k01i*ur;
        float t2r = t1r*k10r - t1i*k10i, t2i = t1r*k10i + t1i*k10r;
        float hr = k00r - t2r, hi = k00i - t2i;
        float dr = shg[2], di = shg[3], dd = shg[4];
        float c2r = 2.0f*dr/dd, c2i = -2.0f*di/dd;
        g_kh[f] = make_float2(c2r*hr - c2i*hi, c2r*hi + c2i*hr);
    }
}

// ---------------- DFT8 butterfly + twiddled scatter ----------------
template<int SWD>
static __device__ __forceinline__ void dft8_store(
    float2 x0, float2 x1, float2 x2, float2 x3,
    float2 x4, float2 x5, float2 x6, float2 x7,
    float2* dst, int o, int s, int ps) {
    float2 ea = cadd(x0, x4), em = csub(x0, x4);
    float2 eb = cadd(x2, x6), en = csub(x2, x6);
    float2 ej = make_float2(-en.y, en.x);
    float2 E0 = cadd(ea, eb), E1 = csub(em, ej);
    float2 E2 = csub(ea, eb), E3 = cadd(em, ej);
    float2 oa = cadd(x1, x5), om = csub(x1, x5);
    float2 ob = cadd(x3, x7), on = csub(x3, x7);
    float2 oj = make_float2(-on.y, on.x);
    float2 O0 = cadd(oa, ob), O1 = csub(om, oj);
    float2 O2 = csub(oa, ob), O3 = cadd(om, oj);
    const float C = 0.70710678118654752440f;
    float2 t0 = O0;
    float2 t1 = make_float2(C*(O1.x + O1.y), C*(O1.y - O1.x));
    float2 t2 = make_float2(O2.y, -O2.x);
    float2 t3 = make_float2(C*(O3.y - O3.x), -C*(O3.x + O3.y));
    float2 X0 = cadd(E0, t0), X4 = csub(E0, t0);
    float2 X1 = cadd(E1, t1), X5 = csub(E1, t1);
    float2 X2 = cadd(E2, t2), X6 = csub(E2, t2);
    float2 X3 = cadd(E3, t3), X7 = csub(E3, t3);
    float sn, cs;
    __sincosf((float)ps * ANG8K, &sn, &cs);
    float2 w1 = make_float2(cs, sn);
    float2 w2 = cmul(w1, w1);
    float2 w3 = cmul(w2, w1);
    float2 w4 = cmul(w2, w2);
    float2 w5 = cmul(w3, w2);
    float2 w6 = cmul(w3, w3);
    float2 w7 = cmul(w4, w3);
    dst[swz<SWD>(o)]       = X0;
    dst[swz<SWD>(o + s)]   = cmul(w1, X1);
    dst[swz<SWD>(o + 2*s)] = cmul(w2, X2);
    dst[swz<SWD>(o + 3*s)] = cmul(w3, X3);
    dst[swz<SWD>(o + 4*s)] = cmul(w4, X4);
    dst[swz<SWD>(o + 5*s)] = cmul(w5, X5);
    dst[swz<SWD>(o + 6*s)] = cmul(w6, X6);
    dst[swz<SWD>(o + 7*s)] = cmul(w7, X7);
}

// In-place staged radix-8 stage: read 16 -> sync -> butterfly+write -> sync.
template<int LS, int SWS, int SWD>
static __device__ __forceinline__ void stage8_ip(float2* C, int tid) {
    float2 r[16];
    #pragma unroll
    for (int it = 0; it < 2; it++) {
        int idx = tid + it * NT;
        #pragma unroll
        for (int m = 0; m < 8; m++)
            r[it*8 + m] = C[swz<SWS>(idx + (m << 10))];
    }
    __syncthreads();
    #pragma unroll
    for (int it = 0; it < 2; it++) {
        int idx = tid + it * NT;
        int p = idx >> LS, q = idx & ((1 << LS) - 1);
        dft8_store<SWD>(r[it*8],r[it*8+1],r[it*8+2],r[it*8+3],
                        r[it*8+4],r[it*8+5],r[it*8+6],r[it*8+7],
                        C, q + (p << (LS + 3)), 1 << LS, p << LS);
    }
    __syncthreads();
}

// Last radix-8 stage (s=512): thread q's read set == write set -> no middle sync.
static __device__ __forceinline__ void stage8_last_ip(float2* C, int q) {
    float2 r[16];
    #pragma unroll
    for (int t = 0; t < 16; t++) r[t] = C[q + (t << 9)];
    #pragma unroll
    for (int p = 0; p < 2; p++) {
        dft8_store<0>(r[p], r[2+p], r[4+p], r[6+p],
                      r[8+p], r[10+p], r[12+p], r[14+p],
                      C, q + (p << 12), 512, p << 9);
    }
    __syncthreads();
}

// stage 0 from gmem (upper half zero), writes T1. Trailing sync.
static __device__ __forceinline__ void stage0_gmem(const float2* __restrict__ xr,
                                                   float2* __restrict__ dst, int tid) {
    const float2 Z = make_float2(0.f, 0.f);
    #pragma unroll
    for (int it = 0; it < 2; it++) {
        int p = tid + it * NT;
        float2 x0 = xr[p];
        float2 x1 = xr[p + 1024];
        float2 x2 = xr[p + 2048];
        float2 x3 = xr[p + 3072];
        dft8_store<1>(x0,x1,x2,x3, Z,Z,Z,Z, dst, p << 3, 1, p);
    }
    __syncthreads();
}

// pointwise pair: writes conj(Zy[k]) to C[k] (and conj(Zy[hk]) to C[hk] if do_h)
static __device__ __forceinline__ void pw_pair(float2* C, int k, int hk,
                                               float2 Zk, float2 Zh, float2 w, bool do_h) {
    float2 Zhc = cconj(Zh);
    float2 E  = cscale(cadd(Zk, Zhc), 0.5f);
    float2 Om = csub(Zk, Zhc);
    float2 O  = make_float2(0.5f * Om.y, -0.5f * Om.x);
    float2 Xk = cadd(E, cmul(w, O));
    float2 wh = make_float2(-w.x, w.y);
    float2 Xh = cadd(cconj(E), cmul(wh, cconj(O)));
    float2 Yk = cmul(Xk, g_kf[k]);
    float2 Yh = cmul(Xh, g_kf[hk]);
    float2 Yhc = cconj(Yh);
    float2 S = cscale(cadd(Yk, Yhc), 0.5f);
    float2 D = cscale(csub(Yk, Yhc), 0.5f);
    float2 u = cmul(cconj(w), D);
    C[k] = cconj(make_float2(S.x - u.y, S.y + u.x));
    if (do_h) {
        float2 Ykc = cconj(Yk);
        float2 S2 = cscale(cadd(Yh, Ykc), 0.5f);
        float2 D2 = cscale(csub(Yh, Ykc), 0.5f);
        float2 v = cmul(w, D2);
        C[hk] = cconj(make_float2(S2.x + v.y, S2.y - v.x));
    }
}

// ---------------- kprep's FFT (table twiddles; validated, two-buffer) ----------------
template<int NTH, bool ZHI, bool SKIPHI>
static __device__ __forceinline__ void fft8192_r8(float2* A, float2* B, int tid) {
    float2* src = A;
    float2* dst = B;
    #pragma unroll
    for (int st = 0; st < 4; st++) {
        const int ls = 3 * st;
        const int s  = 1 << ls;
        #pragma unroll
        for (int it = 0; it < 1024 / NTH; it++) {
            int idx = tid + it * NTH;
            int p = idx >> ls;
            int q = idx & (s - 1);
            float2 x0 = src[idx];
            float2 x1 = src[idx + 1024];
            float2 x2 = src[idx + 2048];
            float2 x3 = src[idx + 3072];
            float2 x4, x5, x6, x7;
            if (ZHI && st == 0) {
                x4 = x5 = x6 = x7 = make_float2(0.f, 0.f);
            } else {
                x4 = src[idx + 4096];
                x5 = src[idx + 5120];
                x6 = src[idx + 6144];
                x7 = src[idx + 7168];
            }
            float2 ea = cadd(x0, x4), em = csub(x0, x4);
            float2 eb = cadd(x2, x6), en = csub(x2, x6);
            float2 ej = make_float2(-en.y, en.x);
            float2 E0 = cadd(ea, eb), E1 = csub(em, ej);
            float2 E2 = csub(ea, eb), E3 = cadd(em, ej);
            float2 oa = cadd(x1, x5), om = csub(x1, x5);
            float2 ob = cadd(x3, x7), on = csub(x3, x7);
            float2 oj = make_float2(-on.y, on.x);
            float2 O0 = cadd(oa, ob), O1 = csub(om, oj);
            float2 O2 = csub(oa, ob), O3 = cadd(om, oj);
            const float C = 0.70710678118654752440f;
            float2 t0 = O0;
            float2 t1 = make_float2(C*(O1.x + O1.y), C*(O1.y - O1.x));
            float2 t2 = make_float2(O2.y, -O2.x);
            float2 t3 = make_float2(C*(O3.y - O3.x), -C*(O3.x + O3.y));
            float2 X0 = cadd(E0, t0), X4 = csub(E0, t0);
            float2 X1 = cadd(E1, t1), X5 = csub(E1, t1);
            float2 X2 = cadd(E2, t2), X6 = csub(E2, t2);
            float2 X3 = cadd(E3, t3), X7 = csub(E3, t3);
            int tw = (p << (ls + 1));
            float2 w1 = g_wm[tw];
            float2 w2 = cmul(w1, w1);
            float2 w3 = cmul(w2, w1);
            float2 w4 = cmul(w2, w2);
            float2 w5 = cmul(w3, w2);
            float2 w6 = cmul(w3, w3);
            float2 w7 = cmul(w4, w3);
            int o = q + (p << (ls + 3));
            dst[o]         = X0;
            dst[o + s]     = cmul(w1, X1);
            dst[o + 2*s]   = cmul(w2, X2);
            dst[o + 3*s]   = cmul(w3, X3);
            dst[o + 4*s]   = cmul(w4, X4);
            dst[o + 5*s]   = cmul(w5, X5);
            dst[o + 6*s]   = cmul(w6, X6);
            dst[o + 7*s]   = cmul(w7, X7);
        }
        __syncthreads();
        float2* t = src; src = dst; dst = t;
    }
    #pragma unroll
    for (int it = 0; it < 4096 / NTH; it++) {
        int q = tid + it * NTH;
        float2 a = src[q], b = src[q + 4096];
        dst[q] = cadd(a, b);
        if (!SKIPHI) dst[q + 4096] = csub(a, b);
    }
    __syncthreads();
}

// ---------------- K preparation (validated) ----------------
__global__ void kprep_kernel() {
    extern __shared__ float2 sm[];
    float2* A = sm;
    float2* B = sm + 8192;
    int tid = threadIdx.x;

    #pragma unroll
    for (int it = 0; it < 16; it++) {
        int f = tid + it * NT;
        float2 kh = (f <= 4096) ? g_kh[f] : g_kh[8192 - f];
        A[f] = (f <= 4096) ? cconj(kh) : kh;
    }
    __syncthreads();
    fft8192_r8<NT, false, false>(A, B, tid);
    const float sc = 1.0f / 8192.0f;
    #pragma unroll
    for (int it = 0; it < 8; it++) {
        int j = tid + it * NT;
        A[j] = make_float2(B[2*j].x * sc, B[2*j + 1].x * sc);
    }
    __syncthreads();
    fft8192_r8<NT, true, false>(A, B, tid);
    for (int k = tid; k <= 4096; k += NT) {
        if (k == 0) {
            float2 Z0 = B[0];
            g_kf[0]    = make_float2(Z0.x + Z0.y, 0.f);
            g_kf[8192] = make_float2(Z0.x - Z0.y, 0.f);
        } else {
            int hk = 8192 - k;
            float2 Zk  = B[k];
            float2 Zhc = cconj(B[hk]);
            float2 E  = cscale(cadd(Zk, Zhc), 0.5f);
            float2 Om = csub(Zk, Zhc);
            float2 O  = make_float2(0.5f * Om.y, -0.5f * Om.x);
            float2 w  = g_wm[k];
            g_kf[k] = cadd(E, cmul(w, O));
            if (k != 4096) {
                float2 wh = make_float2(-w.x, w.y);
                g_kf[hk] = cadd(cconj(E), cmul(wh, cconj(O)));
            }
        }
    }
}

// ---------------- main conv: single 64KB buffer, in-place, 2 blocks/SM ----------------
__global__ void __launch_bounds__(NT, 2) conv_kernel(const float* __restrict__ x,
                                                     float* __restrict__ y) {
    extern __shared__ float2 C[];     // 8192 float2 = 64KB
    int b = blockIdx.x;
    int tid = threadIdx.x;

    const float2* xr = (const float2*)(x + (size_t)b * LSEQ);

    // FFT1
    stage0_gmem(xr, C, tid);          // -> T1
    stage8_ip<3, 1, 2>(C, tid);       // T1 -> T2
    stage8_ip<6, 2, 0>(C, tid);       // T2 -> plain
    stage8_last_ip(C, tid);           // plain -> plain (P, pre final radix-2)

    // pointwise: quad-closed in-place (fused radix-2 of FFT1)
    #pragma unroll
    for (int it = 0; it < 4; it++) {
        int k = tid + it * NT;        // 0..2047
        if (k == 0) {
            // quad {0, 4096}
            float2 P0 = C[0], P4 = C[4096];
            {   // bins 0 / 8192
                float2 Z0 = cadd(P0, P4);
                float X0 = Z0.x + Z0.y;
                float XH = Z0.x - Z0.y;
                float2 Y0 = cscale(g_kf[0], X0);
                float2 YH = cscale(g_kf[8192], XH);
                float2 Yhc = cconj(YH);
                float2 S = cscale(cadd(Y0, Yhc), 0.5f);
                float2 D = cscale(csub(Y0, Yhc), 0.5f);
                C[0] = cconj(make_float2(S.x - D.y, S.y + D.x));
            }
            {   // bin 4096 (self-paired), w = exp(-i*pi/2) = (0,-1)
                float2 Z4 = csub(P0, P4);
                pw_pair(C, 4096, 4096, Z4, Z4, make_float2(0.f, -1.f), false);
            }
            {   // k = 2048 (self-paired quad), w = exp(-i*pi/4)
                float2 Pa = C[2048], Pb = C[6144];
                const float R = 0.70710678118654752440f;
                pw_pair(C, 2048, 6144, cadd(Pa, Pb), csub(Pa, Pb),
                        make_float2(R, -R), true);
            }
        } else {
            int hk = 8192 - k, k2 = 4096 - k, k3 = 4096 + k;
            float2 Pa = C[k], Pb = C[k3], Pc = C[k2], Pd = C[hk];
            float sn, cs;
            __sincosf((float)k * ANG16K, &sn, &cs);
            float2 w = make_float2(cs, sn);
            pw_pair(C, k, hk, cadd(Pa, Pb), csub(Pc, Pd), w, true);
            // w(4096-k) = -i*conj(w) = (-s, -c)
            float2 w2 = make_float2(-sn, -cs);
            pw_pair(C, k2, k3, cadd(Pc, Pd), csub(Pa, Pb), w2, true);
        }
    }
    __syncthreads();

    // IFFT (conj trick; input conj(Zy) in C, plain)
    stage8_ip<0, 0, 1>(C, tid);       // plain -> T1
    stage8_ip<3, 1, 2>(C, tid);       // T1 -> T2
    stage8_ip<6, 2, 0>(C, tid);       // T2 -> plain
    stage8_last_ip(C, tid);           // plain -> plain (pre final radix-2)

    // output: fused final radix-2 (low half) + conj + scale
    float2* yr = (float2*)(y + (size_t)b * LSEQ);
    const float sc = 1.0f / 8192.0f;
    #pragma unroll
    for (int it = 0; it < 8; it++) {
        int j = tid + it * NT;
        float2 f = cadd(C[j], C[j + 4096]);
        yr[j] = make_float2(f.x * sc, -f.y * sc);
    }
}

// ---------------- launch ----------------
extern "C" void kernel_launch(void* const* d_in, const int* in_sizes, int n_in,
                              void* d_out, int out_size) {
    const float* x  = (const float*)d_in[0];
    const float* Bv = (const float*)d_in[1];
    const float* Cv = (const float*)d_in[2];
    float* y = (float*)d_out;
    (void)in_sizes; (void)n_in; (void)out_size;

    const int smem_kprep = 2 * 8192 * (int)sizeof(float2);   // 131072 B
    const int smem_conv  = 8192 * (int)sizeof(float2);       // 65536 B
    cudaFuncSetAttribute(kprep_kernel, cudaFuncAttributeMaxDynamicSharedMemorySize, smem_kprep);
    cudaFuncSetAttribute(conv_kernel,  cudaFuncAttributeMaxDynamicSharedMemorySize, smem_conv);

    setup_kernel<<<4353, 64>>>(Bv, Cv);
    kprep_kernel<<<1, NT, smem_kprep>>>();
    conv_kernel<<<NBATCH, NT, smem_conv>>>(x, y);
}